// round 1
// baseline (speedup 1.0000x reference)
#include <cuda_runtime.h>
#include <math.h>

#define BB 32
#define TT 2048
#define HH 1024

constexpr int BM = 128;
constexpr int BN = 128;
constexpr int BK = 32;
constexpr int NCHUNKS = HH / BN;  // 8

// Scratch (allocation-free rule: __device__ globals)
__device__ float g_decfea[BB * HH];
__device__ float g_scores[BB * TT];

// ---------------------------------------------------------------------------
// Kernel 1: dec_fea[b,d] = sum_h s_t[b,h] * W_s[d,h] + b_s[d]
// grid: 8 blocks (d-chunks of 128), 256 threads
// ---------------------------------------------------------------------------
__global__ void dec_fea_kernel(const float* __restrict__ s_t,
                               const float* __restrict__ W_s,
                               const float* __restrict__ b_s) {
    __shared__ float Ss[BK][BB + 1];    // [k][b]
    __shared__ float Ws[BK][128 + 1];   // [k][d_local]
    const int d0 = blockIdx.x * 128;
    const int tid = threadIdx.x;
    const int dl = tid & 127;
    const int bq = tid >> 7;  // 0..1 -> batches [0,16) or [16,32)

    float acc[16];
#pragma unroll
    for (int i = 0; i < 16; i++) acc[i] = 0.f;

    for (int k0 = 0; k0 < HH; k0 += BK) {
        for (int i = tid; i < BB * BK; i += 256) {
            int bb = i >> 5, kk = i & 31;
            Ss[kk][bb] = s_t[bb * HH + k0 + kk];
        }
        for (int i = tid; i < 128 * BK; i += 256) {
            int dd = i >> 5, kk = i & 31;
            Ws[kk][dd] = W_s[(d0 + dd) * HH + k0 + kk];
        }
        __syncthreads();
#pragma unroll
        for (int kk = 0; kk < BK; kk++) {
            float w = Ws[kk][dl];
#pragma unroll
            for (int i = 0; i < 16; i++)
                acc[i] += w * Ss[kk][bq * 16 + i];
        }
        __syncthreads();
    }
    float bias = b_s[d0 + dl];
#pragma unroll
    for (int i = 0; i < 16; i++)
        g_decfea[(bq * 16 + i) * HH + d0 + dl] = acc[i] + bias;
}

// ---------------------------------------------------------------------------
// Kernel 2: scores[b,t] = sum_d v[d] * tanh( sum_h prev_s[b,t,h]*W_prev[d,h]
//                                            + dec_fea[b,d] )
// Fused GEMM (M=65536, N=1024, K=1024, fp32) + tanh + v-reduction.
// Block: 128 rows (t) x full N (looped in 8 chunks of 128). 256 threads,
// 8x8 microtile per thread.
// ---------------------------------------------------------------------------
__global__ void score_kernel(const float* __restrict__ prev_s,
                             const float* __restrict__ W_prev,
                             const float* __restrict__ v) {
    __shared__ float As[BK][BM + 4];
    __shared__ float Bs[BK][BN + 4];
    __shared__ float red[BM][17];

    const int tid = threadIdx.x;
    const int tx = tid & 15;   // n direction
    const int ty = tid >> 4;   // m direction
    const int row0 = blockIdx.x * BM;       // flat row in [B*T)
    const int b = row0 / TT;                 // 2048 % 128 == 0 -> single b
    const float* __restrict__ dec = g_decfea + b * HH;

    const int mrow = tid >> 3;          // 0..31
    const int kq   = (tid & 7) * 4;     // 0,4,...,28

    float sacc[8];
#pragma unroll
    for (int i = 0; i < 8; i++) sacc[i] = 0.f;

    for (int nc = 0; nc < NCHUNKS; nc++) {
        const int n0 = nc * BN;
        float acc[8][8];
#pragma unroll
        for (int i = 0; i < 8; i++)
#pragma unroll
            for (int j = 0; j < 8; j++) acc[i][j] = 0.f;

        for (int k0 = 0; k0 < HH; k0 += BK) {
#pragma unroll
            for (int s = 0; s < 4; s++) {
                int m = mrow + s * 32;
                float4 av = *reinterpret_cast<const float4*>(
                    &prev_s[(size_t)(row0 + m) * HH + k0 + kq]);
                As[kq + 0][m] = av.x;
                As[kq + 1][m] = av.y;
                As[kq + 2][m] = av.z;
                As[kq + 3][m] = av.w;
                float4 bv = *reinterpret_cast<const float4*>(
                    &W_prev[(size_t)(n0 + m) * HH + k0 + kq]);
                Bs[kq + 0][m] = bv.x;
                Bs[kq + 1][m] = bv.y;
                Bs[kq + 2][m] = bv.z;
                Bs[kq + 3][m] = bv.w;
            }
            __syncthreads();
#pragma unroll
            for (int kk = 0; kk < BK; kk++) {
                float4 a0 = *reinterpret_cast<const float4*>(&As[kk][ty * 8]);
                float4 a1 = *reinterpret_cast<const float4*>(&As[kk][ty * 8 + 4]);
                float4 b0 = *reinterpret_cast<const float4*>(&Bs[kk][tx * 8]);
                float4 b1 = *reinterpret_cast<const float4*>(&Bs[kk][tx * 8 + 4]);
                float ar[8] = {a0.x, a0.y, a0.z, a0.w, a1.x, a1.y, a1.z, a1.w};
                float br[8] = {b0.x, b0.y, b0.z, b0.w, b1.x, b1.y, b1.z, b1.w};
#pragma unroll
                for (int i = 0; i < 8; i++)
#pragma unroll
                    for (int j = 0; j < 8; j++)
                        acc[i][j] += ar[i] * br[j];
            }
            __syncthreads();
        }
        // Epilogue for this n-chunk: tanh + v-weighted reduce over d
#pragma unroll
        for (int j = 0; j < 8; j++) {
            int d = n0 + tx * 8 + j;
            float dj = dec[d];
            float vj = __ldg(&v[d]);
#pragma unroll
            for (int i = 0; i < 8; i++)
                sacc[i] += vj * tanhf(acc[i][j] + dj);
        }
    }

    // Cross-thread reduction over the 16 tx slices per row
#pragma unroll
    for (int i = 0; i < 8; i++)
        red[ty * 8 + i][tx] = sacc[i];
    __syncthreads();
    if (tid < BM) {
        float s = 0.f;
#pragma unroll
        for (int x = 0; x < 16; x++) s += red[tid][x];
        g_scores[row0 + tid] = s;
    }
}

// ---------------------------------------------------------------------------
// Kernel 3: softmax over T per batch (in-place on g_scores)
// ---------------------------------------------------------------------------
__global__ void softmax_kernel() {
    const int b = blockIdx.x;
    const int tid = threadIdx.x;  // 256
    __shared__ float sred[256];
    float* sc = g_scores + b * TT;

    float vals[8];
    float mx = -INFINITY;
#pragma unroll
    for (int i = 0; i < 8; i++) {
        vals[i] = sc[tid + i * 256];
        mx = fmaxf(mx, vals[i]);
    }
    sred[tid] = mx;
    __syncthreads();
    for (int s = 128; s > 0; s >>= 1) {
        if (tid < s) sred[tid] = fmaxf(sred[tid], sred[tid + s]);
        __syncthreads();
    }
    mx = sred[0];
    __syncthreads();

    float sum = 0.f;
#pragma unroll
    for (int i = 0; i < 8; i++) {
        vals[i] = __expf(vals[i] - mx);
        sum += vals[i];
    }
    sred[tid] = sum;
    __syncthreads();
    for (int s = 128; s > 0; s >>= 1) {
        if (tid < s) sred[tid] += sred[tid + s];
        __syncthreads();
    }
    float inv = 1.0f / sred[0];
#pragma unroll
    for (int i = 0; i < 8; i++) sc[tid + i * 256] = vals[i] * inv;
}

// ---------------------------------------------------------------------------
// Zero init of ct_d region (d_out is poisoned to 0xAA)
// ---------------------------------------------------------------------------
__global__ void zero_ct(float* __restrict__ out) {
    int i = blockIdx.x * blockDim.x + threadIdx.x;  // 8192 threads x float4
    reinterpret_cast<float4*>(out)[i] = make_float4(0.f, 0.f, 0.f, 0.f);
}

// ---------------------------------------------------------------------------
// Kernel 4: fused context + concat copy.
//   out[0 : B*H)                    = ct_d[b,h] = sum_t a[b,t]*prev_s[b,t,h]
//   out[B*H : B*H + B*(T+1)*H)      = prev_s_new (prev_s rows + s_t row)
// grid: (17, B); chunks 0..15 handle 128 t-rows each, chunk 16 writes s_t row.
// ---------------------------------------------------------------------------
__global__ void ctx_copy_kernel(const float* __restrict__ prev_s,
                                const float* __restrict__ s_t,
                                float* __restrict__ out) {
    const int b = blockIdx.y;
    const int chunk = blockIdx.x;
    const int tid = threadIdx.x;  // 256 threads x float4 = 1024 floats per row
    float* pn = out + BB * HH;    // prev_s_new base

    if (chunk == 16) {
        float4 sv = reinterpret_cast<const float4*>(s_t + (size_t)b * HH)[tid];
        reinterpret_cast<float4*>(pn + ((size_t)b * (TT + 1) + TT) * HH)[tid] = sv;
        return;
    }

    const int t0 = chunk * 128;
    const float4* src =
        reinterpret_cast<const float4*>(prev_s + ((size_t)b * TT + t0) * HH);
    float4* dst =
        reinterpret_cast<float4*>(pn + ((size_t)b * (TT + 1) + t0) * HH);
    const float* __restrict__ a = g_scores + b * TT + t0;

    float4 acc = make_float4(0.f, 0.f, 0.f, 0.f);
#pragma unroll 4
    for (int t = 0; t < 128; t++) {
        float4 p = src[(size_t)t * 256 + tid];
        dst[(size_t)t * 256 + tid] = p;
        float at = __ldg(&a[t]);
        acc.x += at * p.x;
        acc.y += at * p.y;
        acc.z += at * p.z;
        acc.w += at * p.w;
    }
    float* ctb = out + (size_t)b * HH + tid * 4;
    atomicAdd(ctb + 0, acc.x);
    atomicAdd(ctb + 1, acc.y);
    atomicAdd(ctb + 2, acc.z);
    atomicAdd(ctb + 3, acc.w);
}

// ---------------------------------------------------------------------------
extern "C" void kernel_launch(void* const* d_in, const int* in_sizes, int n_in,
                              void* d_out, int out_size) {
    const float* s_t    = (const float*)d_in[0];
    const float* prev_s = (const float*)d_in[1];
    const float* W_prev = (const float*)d_in[2];
    const float* W_s    = (const float*)d_in[3];
    const float* b_s    = (const float*)d_in[4];
    const float* v      = (const float*)d_in[5];
    float* out = (float*)d_out;

    dec_fea_kernel<<<HH / 128, 256>>>(s_t, W_s, b_s);
    score_kernel<<<(BB * TT) / BM, 256>>>(prev_s, W_prev, v);
    softmax_kernel<<<BB, 256>>>();
    zero_ct<<<32, 256>>>(out);
    dim3 g4(17, BB);
    ctx_copy_kernel<<<g4, 256>>>(prev_s, s_t, out);
}

// round 3
// speedup vs baseline: 2.0857x; 2.0857x over previous
#include <cuda_runtime.h>
#include <cuda_bf16.h>
#include <math.h>
#include <cstdint>

#define BB 32
#define TT 2048
#define HH 1024

// Scratch (allocation-free rule: __device__ globals)
__device__ float g_decfea[BB * HH];
__device__ float g_scores[BB * TT];
// Split planes: per 32-k slab of each row: [32 hi bf16 | 32 lo bf16] = 128B
__device__ __nv_bfloat16 g_B[(size_t)HH * HH * 2];        // W_prev (4 MB)
__device__ __nv_bfloat16 g_A[(size_t)BB * TT * HH * 2];   // prev_s (268 MB)

// ---------------------------------------------------------------------------
// PTX helpers (sm_80-era only: cp.async, ldmatrix, mma.sync — all ok on sm_103)
// ---------------------------------------------------------------------------
__device__ __forceinline__ uint32_t smem_u32(const void* p) {
    uint32_t a;
    asm("{ .reg .u64 t; cvta.to.shared.u64 t, %1; cvt.u32.u64 %0, t; }" : "=r"(a) : "l"(p));
    return a;
}
__device__ __forceinline__ void cp_async16(uint32_t dst, const void* src) {
    asm volatile("cp.async.cg.shared.global [%0], [%1], 16;" :: "r"(dst), "l"(src) : "memory");
}
__device__ __forceinline__ void cp_commit() {
    asm volatile("cp.async.commit_group;" ::: "memory");
}
template <int N>
__device__ __forceinline__ void cp_wait() {
    asm volatile("cp.async.wait_group %0;" :: "n"(N) : "memory");
}
__device__ __forceinline__ void ldsm_x4(uint32_t addr, uint32_t& r0, uint32_t& r1,
                                        uint32_t& r2, uint32_t& r3) {
    asm volatile("ldmatrix.sync.aligned.m8n8.x4.shared.b16 {%0,%1,%2,%3}, [%4];"
                 : "=r"(r0), "=r"(r1), "=r"(r2), "=r"(r3) : "r"(addr));
}
__device__ __forceinline__ void mma16816(float* c, const uint32_t* a, const uint32_t* b) {
    asm volatile(
        "mma.sync.aligned.m16n8k16.row.col.f32.bf16.bf16.f32 "
        "{%0,%1,%2,%3}, {%4,%5,%6,%7}, {%8,%9}, {%0,%1,%2,%3};"
        : "+f"(c[0]), "+f"(c[1]), "+f"(c[2]), "+f"(c[3])
        : "r"(a[0]), "r"(a[1]), "r"(a[2]), "r"(a[3]), "r"(b[0]), "r"(b[1]));
}
__device__ __forceinline__ float fast_tanh(float x) {
    float y;
    asm("tanh.approx.f32 %0, %1;" : "=f"(y) : "f"(x));
    return y;
}
__device__ __forceinline__ uint32_t pack_bf2(__nv_bfloat16 a, __nv_bfloat16 b) {
    __nv_bfloat162 t = __halves2bfloat162(a, b);
    return *reinterpret_cast<uint32_t*>(&t);
}
__device__ __forceinline__ void split2(float x, float y, uint32_t& hi, uint32_t& lo) {
    __nv_bfloat16 hx = __float2bfloat16(x), hy = __float2bfloat16(y);
    __nv_bfloat16 lx = __float2bfloat16(x - __bfloat162float(hx));
    __nv_bfloat16 ly = __float2bfloat16(y - __bfloat162float(hy));
    hi = pack_bf2(hx, hy);
    lo = pack_bf2(lx, ly);
}

// ---------------------------------------------------------------------------
// Split-convert fp32 rows (1024 per row) -> [32 hi | 32 lo] bf16 per 32-slab.
// One thread handles 8 fp32. Launch: nrows*32*4 threads.
// ---------------------------------------------------------------------------
__global__ void conv_split_kernel(const float* __restrict__ src,
                                  __nv_bfloat16* __restrict__ dst) {
    size_t t = (size_t)blockIdx.x * 256 + threadIdx.x;
    int j = (int)(t & 3);
    size_t chunk = t >> 2;  // row*32 + slab
    const float* s = src + chunk * 32 + (size_t)j * 8;
    float4 f0 = *(const float4*)s;
    float4 f1 = *(const float4*)(s + 4);
    uint4 hi, lo;
    split2(f0.x, f0.y, hi.x, lo.x);
    split2(f0.z, f0.w, hi.y, lo.y);
    split2(f1.x, f1.y, hi.z, lo.z);
    split2(f1.z, f1.w, hi.w, lo.w);
    __nv_bfloat16* d = dst + chunk * 64;
    *(uint4*)(d + j * 8) = hi;
    *(uint4*)(d + 32 + j * 8) = lo;
}

// ---------------------------------------------------------------------------
// Kernel 1: dec_fea[b,d] = sum_h s_t[b,h] * W_s[d,h] + b_s[d]   (fp32, small)
// ---------------------------------------------------------------------------
__global__ void dec_fea_kernel(const float* __restrict__ s_t,
                               const float* __restrict__ W_s,
                               const float* __restrict__ b_s) {
    __shared__ float Ss[32][BB + 1];
    __shared__ float Ws[32][128 + 1];
    const int d0 = blockIdx.x * 128;
    const int tid = threadIdx.x;
    const int dl = tid & 127;
    const int bq = tid >> 7;

    float acc[16];
#pragma unroll
    for (int i = 0; i < 16; i++) acc[i] = 0.f;

    for (int k0 = 0; k0 < HH; k0 += 32) {
        for (int i = tid; i < BB * 32; i += 256) {
            int bb = i >> 5, kk = i & 31;
            Ss[kk][bb] = s_t[bb * HH + k0 + kk];
        }
        for (int i = tid; i < 128 * 32; i += 256) {
            int dd = i >> 5, kk = i & 31;
            Ws[kk][dd] = W_s[(d0 + dd) * HH + k0 + kk];
        }
        __syncthreads();
#pragma unroll
        for (int kk = 0; kk < 32; kk++) {
            float w = Ws[kk][dl];
#pragma unroll
            for (int i = 0; i < 16; i++)
                acc[i] += w * Ss[kk][bq * 16 + i];
        }
        __syncthreads();
    }
    float bias = b_s[d0 + dl];
#pragma unroll
    for (int i = 0; i < 16; i++)
        g_decfea[(bq * 16 + i) * HH + d0 + dl] = acc[i] + bias;
}

// ---------------------------------------------------------------------------
// Kernel 2: fused score GEMM via mma.sync bf16x3.
// CTA: 128 M-rows x (8 n-chunks of 128), K in 32-wide double-buffered slabs.
// 8 warps = 2(m) x 4(n); warp tile 64m x 32n; SMEM rows padded to 80B
// (bank-conflict-free ldmatrix: r*20 mod 32 distinct for r=0..7).
// ---------------------------------------------------------------------------
constexpr int A_STAGE = 20480;  // 2 planes * 128 rows * 80B
constexpr int B_OFF = 40960;
constexpr int V_OFF = 81920;
constexpr int DEC_OFF = 86016;
constexpr int RED_OFF = 90112;
constexpr int SMEM_BYTES = 98304;
constexpr int PLANE = 10240;    // 128 rows * 80B

__device__ __forceinline__ void fill_slab(uint32_t sb, int st, int s,
                                          int row0, int n0, int tid) {
#pragma unroll
    for (int it = 0; it < 8; it++) {
        int idx = tid + it * 256;           // 0..2047
        bool isA = idx < 1024;
        int loc = isA ? idx : idx - 1024;
        int m = loc >> 3;
        int p = (loc >> 2) & 1;
        int c = loc & 3;
        const __nv_bfloat16* src =
            (isA ? g_A + ((size_t)(row0 + m) * 32 + s) * 64
                 : g_B + ((size_t)(n0 + m) * 32 + s) * 64) + p * 32 + c * 8;
        uint32_t dst = sb + (isA ? 0u : (uint32_t)B_OFF) + st * A_STAGE +
                       p * PLANE + m * 80 + c * 16;
        cp_async16(dst, src);
    }
}

__global__ void __launch_bounds__(256, 1)
score_kernel(const float* __restrict__ vvec) {
    extern __shared__ char smem[];
    const uint32_t sb = smem_u32(smem);
    const int tid = threadIdx.x;
    const int warp = tid >> 5;
    const int lane = tid & 31;
    const int wm = warp >> 2;   // 0..1
    const int wn = warp & 3;    // 0..3
    const int row0 = blockIdx.x * 128;
    const int b = blockIdx.x >> 4;

    float* v_s = (float*)(smem + V_OFF);
    float* dec_s = (float*)(smem + DEC_OFF);
    for (int i = tid; i < 1024; i += 256) {
        v_s[i] = vvec[i];
        dec_s[i] = g_decfea[b * 1024 + i];
    }
    __syncthreads();

    // ldmatrix lane address components
    const int a_row = wm * 64 + (lane & 15);            // + mt*16
    const int a_col = ((lane >> 4) << 4);               // 0 or 16 bytes
    const int b_row = wn * 32 + (((lane >> 4) & 1) << 3) + (lane & 7);  // + q*16
    const int b_col = (((lane >> 3) & 1) << 4);

    float msum[8];
#pragma unroll
    for (int i = 0; i < 8; i++) msum[i] = 0.f;

#pragma unroll 1
    for (int nc = 0; nc < 8; nc++) {
        const int n0 = nc * 128;
        float acc[4][4][4];
#pragma unroll
        for (int mt = 0; mt < 4; mt++)
#pragma unroll
            for (int nt = 0; nt < 4; nt++)
#pragma unroll
                for (int c = 0; c < 4; c++) acc[mt][nt][c] = 0.f;

        fill_slab(sb, 0, 0, row0, n0, tid);
        cp_commit();

#pragma unroll 1
        for (int s = 0; s < 32; s++) {
            if (s < 31) {
                fill_slab(sb, (s + 1) & 1, s + 1, row0, n0, tid);
                cp_commit();
                cp_wait<1>();
            } else {
                cp_wait<0>();
            }
            __syncthreads();

            const uint32_t abase = sb + (uint32_t)((s & 1) * A_STAGE);
            const uint32_t bbase = sb + (uint32_t)(B_OFF + (s & 1) * A_STAGE);
#pragma unroll
            for (int ks = 0; ks < 2; ks++) {
                uint32_t ah[4][4], al[4][4], bh[4][2], bl[4][2];
#pragma unroll
                for (int mt = 0; mt < 4; mt++) {
                    uint32_t ra = abase + (a_row + mt * 16) * 80 + a_col + ks * 32;
                    ldsm_x4(ra, ah[mt][0], ah[mt][1], ah[mt][2], ah[mt][3]);
                    ldsm_x4(ra + PLANE, al[mt][0], al[mt][1], al[mt][2], al[mt][3]);
                }
#pragma unroll
                for (int q = 0; q < 2; q++) {
                    uint32_t rb = bbase + (b_row + q * 16) * 80 + b_col + ks * 32;
                    uint32_t r0, r1, r2, r3;
                    ldsm_x4(rb, r0, r1, r2, r3);
                    bh[2 * q][0] = r0; bh[2 * q][1] = r1;
                    bh[2 * q + 1][0] = r2; bh[2 * q + 1][1] = r3;
                    ldsm_x4(rb + PLANE, r0, r1, r2, r3);
                    bl[2 * q][0] = r0; bl[2 * q][1] = r1;
                    bl[2 * q + 1][0] = r2; bl[2 * q + 1][1] = r3;
                }
#pragma unroll
                for (int mt = 0; mt < 4; mt++)
#pragma unroll
                    for (int nt = 0; nt < 4; nt++)
                        mma16816(acc[mt][nt], ah[mt], bh[nt]);
#pragma unroll
                for (int mt = 0; mt < 4; mt++)
#pragma unroll
                    for (int nt = 0; nt < 4; nt++)
                        mma16816(acc[mt][nt], ah[mt], bl[nt]);
#pragma unroll
                for (int mt = 0; mt < 4; mt++)
#pragma unroll
                    for (int nt = 0; nt < 4; nt++)
                        mma16816(acc[mt][nt], al[mt], bh[nt]);
            }
            __syncthreads();
        }

        // Epilogue: msum[m-slot] += v[d]*tanh(acc + dec[d])
#pragma unroll
        for (int nt = 0; nt < 4; nt++) {
#pragma unroll
            for (int j = 0; j < 2; j++) {
                int d = n0 + wn * 32 + nt * 8 + 2 * (lane & 3) + j;
                float vd = v_s[d];
                float dj = dec_s[d];
#pragma unroll
                for (int mt = 0; mt < 4; mt++) {
#pragma unroll
                    for (int h = 0; h < 2; h++) {
                        float x = acc[mt][nt][h * 2 + j] + dj;
                        msum[mt * 2 + h] += vd * fast_tanh(x);
                    }
                }
            }
        }
    }

    // Cross-warp reduction: red[m][wn*4 + lane%4]
    float* red = (float*)(smem + RED_OFF);
#pragma unroll
    for (int mt = 0; mt < 4; mt++)
#pragma unroll
        for (int h = 0; h < 2; h++) {
            int m = wm * 64 + mt * 16 + h * 8 + (lane >> 2);
            red[m * 16 + wn * 4 + (lane & 3)] = msum[mt * 2 + h];
        }
    __syncthreads();
    if (tid < 128) {
        float sum = 0.f;
#pragma unroll
        for (int x = 0; x < 16; x++) sum += red[tid * 16 + x];
        g_scores[row0 + tid] = sum;
    }
}

// ---------------------------------------------------------------------------
// Kernel 3: softmax over T per batch (in-place on g_scores)
// ---------------------------------------------------------------------------
__global__ void softmax_kernel() {
    const int b = blockIdx.x;
    const int tid = threadIdx.x;  // 256
    __shared__ float sred[256];
    float* sc = g_scores + b * TT;

    float vals[8];
    float mx = -INFINITY;
#pragma unroll
    for (int i = 0; i < 8; i++) {
        vals[i] = sc[tid + i * 256];
        mx = fmaxf(mx, vals[i]);
    }
    sred[tid] = mx;
    __syncthreads();
    for (int s = 128; s > 0; s >>= 1) {
        if (tid < s) sred[tid] = fmaxf(sred[tid], sred[tid + s]);
        __syncthreads();
    }
    mx = sred[0];
    __syncthreads();

    float sum = 0.f;
#pragma unroll
    for (int i = 0; i < 8; i++) {
        vals[i] = __expf(vals[i] - mx);
        sum += vals[i];
    }
    sred[tid] = sum;
    __syncthreads();
    for (int s = 128; s > 0; s >>= 1) {
        if (tid < s) sred[tid] += sred[tid + s];
        __syncthreads();
    }
    float inv = 1.0f / sred[0];
#pragma unroll
    for (int i = 0; i < 8; i++) sc[tid + i * 256] = vals[i] * inv;
}

// ---------------------------------------------------------------------------
// Zero init of ct_d region (d_out is poisoned to 0xAA)
// ---------------------------------------------------------------------------
__global__ void zero_ct(float* __restrict__ out) {
    int i = blockIdx.x * blockDim.x + threadIdx.x;
    reinterpret_cast<float4*>(out)[i] = make_float4(0.f, 0.f, 0.f, 0.f);
}

// ---------------------------------------------------------------------------
// Kernel 4: fused context + concat copy.
// ---------------------------------------------------------------------------
__global__ void ctx_copy_kernel(const float* __restrict__ prev_s,
                                const float* __restrict__ s_t,
                                float* __restrict__ out) {
    const int b = blockIdx.y;
    const int chunk = blockIdx.x;
    const int tid = threadIdx.x;
    float* pn = out + BB * HH;

    if (chunk == 16) {
        float4 sv = reinterpret_cast<const float4*>(s_t + (size_t)b * HH)[tid];
        reinterpret_cast<float4*>(pn + ((size_t)b * (TT + 1) + TT) * HH)[tid] = sv;
        return;
    }

    const int t0 = chunk * 128;
    const float4* src =
        reinterpret_cast<const float4*>(prev_s + ((size_t)b * TT + t0) * HH);
    float4* dst =
        reinterpret_cast<float4*>(pn + ((size_t)b * (TT + 1) + t0) * HH);
    const float* __restrict__ a = g_scores + b * TT + t0;

    float4 acc = make_float4(0.f, 0.f, 0.f, 0.f);
#pragma unroll 4
    for (int t = 0; t < 128; t++) {
        float4 p = src[(size_t)t * 256 + tid];
        dst[(size_t)t * 256 + tid] = p;
        float at = __ldg(&a[t]);
        acc.x += at * p.x;
        acc.y += at * p.y;
        acc.z += at * p.z;
        acc.w += at * p.w;
    }
    float* ctb = out + (size_t)b * HH + tid * 4;
    atomicAdd(ctb + 0, acc.x);
    atomicAdd(ctb + 1, acc.y);
    atomicAdd(ctb + 2, acc.z);
    atomicAdd(ctb + 3, acc.w);
}

// ---------------------------------------------------------------------------
extern "C" void kernel_launch(void* const* d_in, const int* in_sizes, int n_in,
                              void* d_out, int out_size) {
    const float* s_t    = (const float*)d_in[0];
    const float* prev_s = (const float*)d_in[1];
    const float* W_prev = (const float*)d_in[2];
    const float* W_s    = (const float*)d_in[3];
    const float* b_s    = (const float*)d_in[4];
    const float* v      = (const float*)d_in[5];
    float* out = (float*)d_out;

    cudaFuncSetAttribute(score_kernel,
                         cudaFuncAttributeMaxDynamicSharedMemorySize, SMEM_BYTES);

    __nv_bfloat16 *gA, *gB;
    cudaGetSymbolAddress((void**)&gA, g_A);
    cudaGetSymbolAddress((void**)&gB, g_B);

    conv_split_kernel<<<512, 256>>>(W_prev, gB);                       // B: 1024 rows
    conv_split_kernel<<<32768, 256>>>(prev_s, gA);                     // A: 65536 rows
    dec_fea_kernel<<<HH / 128, 256>>>(s_t, W_s, b_s);
    score_kernel<<<(BB * TT) / 128, 256, SMEM_BYTES>>>(v);
    softmax_kernel<<<BB, 256>>>();
    zero_ct<<<32, 256>>>(out);
    dim3 g4(17, BB);
    ctx_copy_kernel<<<g4, 256>>>(prev_s, s_t, out);
}